// round 1
// baseline (speedup 1.0000x reference)
#include <cuda_runtime.h>
#include <cstdint>

#define N_NODES_MAX 100000
#define N_EDGES_MAX 1600000
#define N_GRAPHS_MAX 512

// ---------------- scratch (device globals; no allocation allowed) ----------
__device__ __align__(16) float g_h0[N_NODES_MAX * 32];
__device__ __align__(16) float g_h1[N_NODES_MAX * 64];
__device__ __align__(16) float g_h2[N_NODES_MAX * 64];
__device__ int   g_deg[N_NODES_MAX];
__device__ int   g_rowptr[N_NODES_MAX + 1];
__device__ int   g_wp[N_NODES_MAX];
__device__ int   g_src_sorted[N_EDGES_MAX];
__device__ __align__(16) float g_gsum[N_GRAPHS_MAX * 64];
__device__ int   g_gcnt[N_GRAPHS_MAX];

// ---------------- zero scratch ----------------------------------------------
__global__ void zero_kernel(int n, int g) {
    int i = blockIdx.x * blockDim.x + threadIdx.x;
    int stride = gridDim.x * blockDim.x;
    for (int j = i; j < n; j += stride) g_deg[j] = 0;
    for (int j = i; j < g; j += stride) g_gcnt[j] = 0;
    for (int j = i; j < g * 64; j += stride) g_gsum[j] = 0.f;
}

// ---------------- degree count ----------------------------------------------
__global__ void degree_kernel(const int* __restrict__ dst, int E) {
    int e = blockIdx.x * blockDim.x + threadIdx.x;
    if (e < E) atomicAdd(&g_deg[dst[e]], 1);
}

// ---------------- single-block exclusive scan (shfl-based) ------------------
__global__ void scan_kernel(int n) {
    __shared__ int warpsums[32];
    __shared__ int s_carry;
    int t = threadIdx.x, lane = t & 31, w = t >> 5;
    if (t == 0) s_carry = 0;
    __syncthreads();
    for (int base = 0; base < n; base += 1024) {
        int i = base + t;
        int v = (i < n) ? g_deg[i] : 0;
        int x = v;
        #pragma unroll
        for (int off = 1; off < 32; off <<= 1) {
            int u = __shfl_up_sync(0xFFFFFFFFu, x, off);
            if (lane >= off) x += u;
        }
        if (lane == 31) warpsums[w] = x;
        __syncthreads();
        if (w == 0) {
            int y = warpsums[lane];
            #pragma unroll
            for (int off = 1; off < 32; off <<= 1) {
                int u = __shfl_up_sync(0xFFFFFFFFu, y, off);
                if (lane >= off) y += u;
            }
            warpsums[lane] = y;
        }
        __syncthreads();
        int woff = (w > 0) ? warpsums[w - 1] : 0;
        int exc = x + woff - v + s_carry;
        if (i < n) { g_rowptr[i] = exc; g_wp[i] = exc; }
        __syncthreads();
        if (t == 0) s_carry += warpsums[31];
        __syncthreads();
    }
    if (t == 0) g_rowptr[n] = s_carry;
}

// ---------------- bucket edges by dst ----------------------------------------
__global__ void bucket_kernel(const int* __restrict__ src,
                              const int* __restrict__ dst, int E) {
    int e = blockIdx.x * blockDim.x + threadIdx.x;
    if (e < E) {
        int d = dst[e];
        int p = atomicAdd(&g_wp[d], 1);
        g_src_sorted[p] = src[e];
    }
}

// ---------------- pre MLP: x[N,5] @ W[5,32] + b, relu ------------------------
__global__ void pre_kernel(const float* __restrict__ x,
                           const float* __restrict__ w,
                           const float* __restrict__ b, int n) {
    int tid = blockIdx.x * blockDim.x + threadIdx.x;
    if (tid >= n * 32) return;
    int node = tid >> 5, j = tid & 31;
    const float* xr = x + node * 5;
    float acc = __ldg(&b[j]);
    #pragma unroll
    for (int k = 0; k < 5; k++) acc += xr[k] * __ldg(&w[k * 32 + j]);
    g_h0[tid] = fmaxf(acc, 0.f);
}

// ---------------- fused SAGE conv: gather-mean + dual matmul + L2norm + relu -
// LAYER 1: IN=32, h0 -> h1 ; LAYER 2: IN=64, h1 -> h2. OUT=64 both.
// One warp per node. Weights packed float4 {wl[k][2o],wr[k][2o],wl[k][2o+1],wr[k][2o+1]}.
template <int LAYER>
__global__ __launch_bounds__(256) void conv_kernel(
    const float* __restrict__ wl, const float* __restrict__ bl,
    const float* __restrict__ wr, int n)
{
    constexpr int IN = (LAYER == 1) ? 32 : 64;
    const float* __restrict__ hin  = (LAYER == 1) ? g_h0 : g_h1;
    float* __restrict__       hout = (LAYER == 1) ? g_h1 : g_h2;

    __shared__ float4 sw4[IN * 32];
    __shared__ float  sb[64];
    for (int i = threadIdx.x; i < IN * 32; i += blockDim.x) {
        int k = i >> 5, o2 = (i & 31) * 2;
        sw4[i] = make_float4(wl[k * 64 + o2],     wr[k * 64 + o2],
                             wl[k * 64 + o2 + 1], wr[k * 64 + o2 + 1]);
    }
    if (threadIdx.x < 64) sb[threadIdx.x] = bl[threadIdx.x];
    __syncthreads();

    int warp = threadIdx.x >> 5, lane = threadIdx.x & 31;
    int node = blockIdx.x * (blockDim.x >> 5) + warp;
    if (node >= n) return;

    int s0 = g_rowptr[node], s1 = g_rowptr[node + 1];
    float acc0, acc1;

    if constexpr (LAYER == 1) {
        float a = 0.f;
        int e = s0;
        for (; e + 4 <= s1; e += 4) {
            int sa = g_src_sorted[e],     sbi = g_src_sorted[e + 1];
            int sc = g_src_sorted[e + 2], sd  = g_src_sorted[e + 3];
            float va = hin[sa * 32 + lane], vb = hin[sbi * 32 + lane];
            float vc = hin[sc * 32 + lane], vd = hin[sd * 32 + lane];
            a += (va + vb) + (vc + vd);
        }
        for (; e < s1; e++) a += hin[g_src_sorted[e] * 32 + lane];
        float cnt = (float)(s1 - s0);
        a = (s1 > s0) ? a / cnt : 0.f;
        float h = hin[node * 32 + lane];

        acc0 = sb[2 * lane]; acc1 = sb[2 * lane + 1];
        #pragma unroll
        for (int k = 0; k < 32; k++) {
            float ak = __shfl_sync(0xFFFFFFFFu, a, k);
            float hk = __shfl_sync(0xFFFFFFFFu, h, k);
            float4 w = sw4[k * 32 + lane];
            acc0 += ak * w.x + hk * w.y;
            acc1 += ak * w.z + hk * w.w;
        }
    } else {
        float ax_ = 0.f, ay_ = 0.f;
        int e = s0;
        for (; e + 2 <= s1; e += 2) {
            int sa = g_src_sorted[e], sbi = g_src_sorted[e + 1];
            float2 va = *(const float2*)&hin[sa * 64 + 2 * lane];
            float2 vb = *(const float2*)&hin[sbi * 64 + 2 * lane];
            ax_ += va.x + vb.x; ay_ += va.y + vb.y;
        }
        for (; e < s1; e++) {
            float2 v = *(const float2*)&hin[g_src_sorted[e] * 64 + 2 * lane];
            ax_ += v.x; ay_ += v.y;
        }
        float cnt = (float)(s1 - s0);
        float inv = (s1 > s0) ? 1.f / cnt : 0.f;
        ax_ *= inv; ay_ *= inv;
        float2 h = *(const float2*)&hin[node * 64 + 2 * lane];

        acc0 = sb[2 * lane]; acc1 = sb[2 * lane + 1];
        #pragma unroll
        for (int kp = 0; kp < 32; kp++) {
            float axk = __shfl_sync(0xFFFFFFFFu, ax_, kp);
            float ayk = __shfl_sync(0xFFFFFFFFu, ay_, kp);
            float hxk = __shfl_sync(0xFFFFFFFFu, h.x, kp);
            float hyk = __shfl_sync(0xFFFFFFFFu, h.y, kp);
            float4 w0 = sw4[(2 * kp) * 32 + lane];
            float4 w1 = sw4[(2 * kp + 1) * 32 + lane];
            acc0 += axk * w0.x + hxk * w0.y + ayk * w1.x + hyk * w1.y;
            acc1 += axk * w0.z + hxk * w0.w + ayk * w1.z + hyk * w1.w;
        }
    }

    // L2 normalize across 64 outputs (acc0, acc1 per lane), then relu
    float ss = acc0 * acc0 + acc1 * acc1;
    #pragma unroll
    for (int off = 16; off; off >>= 1) ss += __shfl_xor_sync(0xFFFFFFFFu, ss, off);
    float nrm = sqrtf(ss);
    float inv = 1.f / fmaxf(nrm, 1e-12f);
    acc0 = fmaxf(acc0 * inv, 0.f);
    acc1 = fmaxf(acc1 * inv, 0.f);
    *(float2*)&hout[node * 64 + 2 * lane] = make_float2(acc0, acc1);
}

// ---------------- global mean pool (atomic scatter) --------------------------
__global__ void pool_kernel(const int* __restrict__ batch, int n) {
    int tid = blockIdx.x * blockDim.x + threadIdx.x;
    if (tid >= n * 64) return;
    int node = tid >> 6, j = tid & 63;
    int b = batch[node];
    atomicAdd(&g_gsum[b * 64 + j], g_h2[tid]);
    if (j == 0) atomicAdd(&g_gcnt[b], 1);
}

// ---------------- head MLP: 64 -> 64 -> 16 -> 1 ------------------------------
__global__ void head_kernel(const float* __restrict__ p1w, const float* __restrict__ p1b,
                            const float* __restrict__ p2w, const float* __restrict__ p2b,
                            const float* __restrict__ ow,  const float* __restrict__ ob,
                            float* __restrict__ out) {
    int g = blockIdx.x, t = threadIdx.x;  // 64 threads
    __shared__ float sg[64], s1[64], s2[16];
    float c = (float)g_gcnt[g];
    float invc = 1.f / fmaxf(c, 1.f);
    sg[t] = g_gsum[g * 64 + t] * invc;
    __syncthreads();
    float acc = __ldg(&p1b[t]);
    #pragma unroll 8
    for (int k = 0; k < 64; k++) acc += sg[k] * __ldg(&p1w[k * 64 + t]);
    s1[t] = fmaxf(acc, 0.f);
    __syncthreads();
    if (t < 16) {
        float a2 = __ldg(&p2b[t]);
        #pragma unroll 8
        for (int k = 0; k < 64; k++) a2 += s1[k] * __ldg(&p2w[k * 16 + t]);
        s2[t] = fmaxf(a2, 0.f);
    }
    __syncthreads();
    if (t == 0) {
        float o = __ldg(&ob[0]);
        #pragma unroll
        for (int k = 0; k < 16; k++) o += s2[k] * __ldg(&ow[k]);
        out[g] = o;
    }
}

// ---------------- launcher ---------------------------------------------------
extern "C" void kernel_launch(void* const* d_in, const int* in_sizes, int n_in,
                              void* d_out, int out_size) {
    const float* x     = (const float*)d_in[0];
    const int*   ei    = (const int*)d_in[1];
    const int*   batch = (const int*)d_in[2];
    // d_in[3] = num_graphs (scalar), unused
    const float* pre_w = (const float*)d_in[4];
    const float* pre_b = (const float*)d_in[5];
    const float* c1_wl = (const float*)d_in[6];
    const float* c1_bl = (const float*)d_in[7];
    const float* c1_wr = (const float*)d_in[8];
    const float* c2_wl = (const float*)d_in[9];
    const float* c2_bl = (const float*)d_in[10];
    const float* c2_wr = (const float*)d_in[11];
    const float* p1_w  = (const float*)d_in[12];
    const float* p1_b  = (const float*)d_in[13];
    const float* p2_w  = (const float*)d_in[14];
    const float* p2_b  = (const float*)d_in[15];
    const float* o_w   = (const float*)d_in[16];
    const float* o_b   = (const float*)d_in[17];

    int n = in_sizes[0] / 5;          // nodes
    int E = in_sizes[1] / 2;          // edges
    int G = out_size;                 // graphs
    const int* src = ei;
    const int* dst = ei + E;
    float* out = (float*)d_out;

    zero_kernel<<<(n + 255) / 256, 256>>>(n, G);
    degree_kernel<<<(E + 255) / 256, 256>>>(dst, E);
    scan_kernel<<<1, 1024>>>(n);
    bucket_kernel<<<(E + 255) / 256, 256>>>(src, dst, E);
    pre_kernel<<<(n * 32 + 255) / 256, 256>>>(x, pre_w, pre_b, n);
    conv_kernel<1><<<(n + 7) / 8, 256>>>(c1_wl, c1_bl, c1_wr, n);
    conv_kernel<2><<<(n + 7) / 8, 256>>>(c2_wl, c2_bl, c2_wr, n);
    pool_kernel<<<(n * 64 + 255) / 256, 256>>>(batch, n);
    head_kernel<<<G, 64>>>(p1_w, p1_b, p2_w, p2_b, o_w, o_b, out);
}

// round 2
// speedup vs baseline: 1.5785x; 1.5785x over previous
#include <cuda_runtime.h>
#include <cstdint>

#define N_NODES_MAX 100000
#define N_EDGES_MAX 1600000
#define N_GRAPHS_MAX 512

// ---------------- scratch (device globals; no allocation allowed) ----------
__device__ __align__(16) float g_h0[N_NODES_MAX * 32];
__device__ __align__(16) float g_h1[N_NODES_MAX * 64];
__device__ __align__(16) float g_h2[N_NODES_MAX * 64];
__device__ int   g_deg[N_NODES_MAX];
__device__ int   g_rowptr[N_NODES_MAX + 1];
__device__ int   g_wp[N_NODES_MAX];
__device__ int   g_src_sorted[N_EDGES_MAX];
__device__ int   g_bsum[1024];
__device__ int   g_boff[1024];
__device__ __align__(16) float g_gsum[N_GRAPHS_MAX * 64];
__device__ int   g_gcnt[N_GRAPHS_MAX];

// ---------------- zero scratch ----------------------------------------------
__global__ void zero_kernel(int n, int g) {
    int i = blockIdx.x * blockDim.x + threadIdx.x;
    int stride = gridDim.x * blockDim.x;
    for (int j = i; j < n; j += stride) g_deg[j] = 0;
    for (int j = i; j < g; j += stride) g_gcnt[j] = 0;
    for (int j = i; j < g * 64; j += stride) g_gsum[j] = 0.f;
}

// ---------------- degree count ----------------------------------------------
__global__ void degree_kernel(const int* __restrict__ dst, int E) {
    int e = blockIdx.x * blockDim.x + threadIdx.x;
    if (e < E) atomicAdd(&g_deg[dst[e]], 1);
}

// ---------------- multi-block scan, pass 1: per-block (1024) local scan ------
__global__ void scan1_kernel(int n) {
    __shared__ int warpsums[32];
    int t = threadIdx.x, lane = t & 31, w = t >> 5;
    int i = blockIdx.x * 1024 + t;
    int v = (i < n) ? g_deg[i] : 0;
    int x = v;
    #pragma unroll
    for (int off = 1; off < 32; off <<= 1) {
        int u = __shfl_up_sync(0xFFFFFFFFu, x, off);
        if (lane >= off) x += u;
    }
    if (lane == 31) warpsums[w] = x;
    __syncthreads();
    if (w == 0) {
        int y = warpsums[lane];
        #pragma unroll
        for (int off = 1; off < 32; off <<= 1) {
            int u = __shfl_up_sync(0xFFFFFFFFu, y, off);
            if (lane >= off) y += u;
        }
        warpsums[lane] = y;
    }
    __syncthreads();
    int woff = (w > 0) ? warpsums[w - 1] : 0;
    if (i < n) g_rowptr[i] = x + woff - v;   // local exclusive
    if (t == 0) g_bsum[blockIdx.x] = warpsums[31];
}

// ---------------- scan pass 2: scan the block sums (<=1024 blocks) ----------
__global__ void scan2_kernel(int nb, int n) {
    __shared__ int warpsums[32];
    int t = threadIdx.x, lane = t & 31, w = t >> 5;
    int v = (t < nb) ? g_bsum[t] : 0;
    int x = v;
    #pragma unroll
    for (int off = 1; off < 32; off <<= 1) {
        int u = __shfl_up_sync(0xFFFFFFFFu, x, off);
        if (lane >= off) x += u;
    }
    if (lane == 31) warpsums[w] = x;
    __syncthreads();
    if (w == 0) {
        int y = warpsums[lane];
        #pragma unroll
        for (int off = 1; off < 32; off <<= 1) {
            int u = __shfl_up_sync(0xFFFFFFFFu, y, off);
            if (lane >= off) y += u;
        }
        warpsums[lane] = y;
    }
    __syncthreads();
    int woff = (w > 0) ? warpsums[w - 1] : 0;
    if (t < nb) g_boff[t] = x + woff - v;
    if (t == 0) g_rowptr[n] = warpsums[31];
}

// ---------------- scan pass 3: add block offsets -----------------------------
__global__ void scan3_kernel(int n) {
    int i = blockIdx.x * blockDim.x + threadIdx.x;
    if (i < n) {
        int v = g_rowptr[i] + g_boff[i >> 10];
        g_rowptr[i] = v;
        g_wp[i] = v;
    }
}

// ---------------- bucket edges by dst ----------------------------------------
__global__ void bucket_kernel(const int* __restrict__ src,
                              const int* __restrict__ dst, int E) {
    int e = blockIdx.x * blockDim.x + threadIdx.x;
    if (e < E) {
        int d = dst[e];
        int p = atomicAdd(&g_wp[d], 1);
        g_src_sorted[p] = src[e];
    }
}

// ---------------- pre MLP: x[N,5] @ W[5,32] + b, relu ------------------------
__global__ void pre_kernel(const float* __restrict__ x,
                           const float* __restrict__ w,
                           const float* __restrict__ b, int n) {
    int tid = blockIdx.x * blockDim.x + threadIdx.x;
    if (tid >= n * 32) return;
    int node = tid >> 5, j = tid & 31;
    const float* xr = x + node * 5;
    float acc = __ldg(&b[j]);
    #pragma unroll
    for (int k = 0; k < 5; k++) acc += xr[k] * __ldg(&w[k * 32 + j]);
    g_h0[tid] = fmaxf(acc, 0.f);
}

// ---------------- fused SAGE conv --------------------------------------------
// 2 nodes per warp. (a,h) staged in per-warp smem, broadcast via LDS.128.
// Weights packed float4 {wl[k][2o], wr[k][2o], wl[k][2o+1], wr[k][2o+1]}.
template <int LAYER>
__global__ __launch_bounds__(256) void conv_kernel(
    const float* __restrict__ wl, const float* __restrict__ bl,
    const float* __restrict__ wr, int n)
{
    constexpr int IN = (LAYER == 1) ? 32 : 64;
    const float* __restrict__ hin  = (LAYER == 1) ? g_h0 : g_h1;
    float* __restrict__       hout = (LAYER == 1) ? g_h1 : g_h2;

    __shared__ float4 sw4[IN * 32];
    __shared__ float  sb[64];
    __shared__ float4 sAH[8][2][32];

    for (int i = threadIdx.x; i < IN * 32; i += blockDim.x) {
        int k = i >> 5, o2 = (i & 31) * 2;
        sw4[i] = make_float4(wl[k * 64 + o2],     wr[k * 64 + o2],
                             wl[k * 64 + o2 + 1], wr[k * 64 + o2 + 1]);
    }
    if (threadIdx.x < 64) sb[threadIdx.x] = bl[threadIdx.x];
    __syncthreads();

    int warp = threadIdx.x >> 5, lane = threadIdx.x & 31;
    int node0 = blockIdx.x * 16 + warp * 2;
    if (node0 >= n) return;
    int node1 = node0 + 1;
    bool hasB = (node1 < n);

    // ---- gather + stage ----
    #pragma unroll
    for (int t = 0; t < 2; t++) {
        int node = node0 + t;
        if (t == 1 && !hasB) break;
        int s0 = g_rowptr[node], s1 = g_rowptr[node + 1];
        if constexpr (LAYER == 1) {
            float a = 0.f;
            int e = s0;
            for (; e + 4 <= s1; e += 4) {
                int sa = g_src_sorted[e],     sbi = g_src_sorted[e + 1];
                int sc = g_src_sorted[e + 2], sd  = g_src_sorted[e + 3];
                a += (hin[sa * 32 + lane] + hin[sbi * 32 + lane])
                   + (hin[sc * 32 + lane] + hin[sd * 32 + lane]);
            }
            for (; e < s1; e++) a += hin[g_src_sorted[e] * 32 + lane];
            float inv = (s1 > s0) ? 1.f / (float)(s1 - s0) : 0.f;
            a *= inv;
            float h = hin[node * 32 + lane];
            sAH[warp][t][lane] = make_float4(a, h, 0.f, 0.f);
        } else {
            float ax_ = 0.f, ay_ = 0.f;
            int e = s0;
            for (; e + 2 <= s1; e += 2) {
                int sa = g_src_sorted[e], sbi = g_src_sorted[e + 1];
                float2 va = *(const float2*)&hin[sa * 64 + 2 * lane];
                float2 vb = *(const float2*)&hin[sbi * 64 + 2 * lane];
                ax_ += va.x + vb.x; ay_ += va.y + vb.y;
            }
            for (; e < s1; e++) {
                float2 v = *(const float2*)&hin[g_src_sorted[e] * 64 + 2 * lane];
                ax_ += v.x; ay_ += v.y;
            }
            float inv = (s1 > s0) ? 1.f / (float)(s1 - s0) : 0.f;
            ax_ *= inv; ay_ *= inv;
            float2 h = *(const float2*)&hin[node * 64 + 2 * lane];
            sAH[warp][t][lane] = make_float4(ax_, ay_, h.x, h.y);
        }
    }
    __syncwarp();

    // ---- dual matmul for both nodes ----
    float accA0 = sb[2 * lane], accA1 = sb[2 * lane + 1];
    float accB0 = accA0,        accB1 = accA1;

    if constexpr (LAYER == 1) {
        #pragma unroll
        for (int k = 0; k < 32; k++) {
            float4 w = sw4[k * 32 + lane];
            float4 A = sAH[warp][0][k];
            float4 B = sAH[warp][1][k];
            accA0 += A.x * w.x + A.y * w.y;
            accA1 += A.x * w.z + A.y * w.w;
            accB0 += B.x * w.x + B.y * w.y;
            accB1 += B.x * w.z + B.y * w.w;
        }
    } else {
        #pragma unroll
        for (int kp = 0; kp < 32; kp++) {
            float4 w0 = sw4[(2 * kp) * 32 + lane];
            float4 w1 = sw4[(2 * kp + 1) * 32 + lane];
            float4 A = sAH[warp][0][kp];
            float4 B = sAH[warp][1][kp];
            accA0 += A.x * w0.x + A.z * w0.y + A.y * w1.x + A.w * w1.y;
            accA1 += A.x * w0.z + A.z * w0.w + A.y * w1.z + A.w * w1.w;
            accB0 += B.x * w0.x + B.z * w0.y + B.y * w1.x + B.w * w1.y;
            accB1 += B.x * w0.z + B.z * w0.w + B.y * w1.z + B.w * w1.w;
        }
    }

    // ---- L2 norm + relu + store ----
    float ssA = accA0 * accA0 + accA1 * accA1;
    float ssB = accB0 * accB0 + accB1 * accB1;
    #pragma unroll
    for (int off = 16; off; off >>= 1) {
        ssA += __shfl_xor_sync(0xFFFFFFFFu, ssA, off);
        ssB += __shfl_xor_sync(0xFFFFFFFFu, ssB, off);
    }
    float invA = 1.f / fmaxf(sqrtf(ssA), 1e-12f);
    *(float2*)&hout[node0 * 64 + 2 * lane] =
        make_float2(fmaxf(accA0 * invA, 0.f), fmaxf(accA1 * invA, 0.f));
    if (hasB) {
        float invB = 1.f / fmaxf(sqrtf(ssB), 1e-12f);
        *(float2*)&hout[node1 * 64 + 2 * lane] =
            make_float2(fmaxf(accB0 * invB, 0.f), fmaxf(accB1 * invB, 0.f));
    }
}

// ---------------- segmented global mean pool (batch is sorted) ---------------
#define POOL_R 128
__global__ void pool_kernel(const int* __restrict__ batch, int n) {
    int t = threadIdx.x;  // 64 threads = 64 features
    int start = blockIdx.x * POOL_R;
    int end = min(start + POOL_R, n);
    if (start >= end) return;
    int cur = batch[start];
    float acc = 0.f;
    int cnt = 0;
    for (int node = start; node < end; node++) {
        int b = batch[node];
        if (b != cur) {
            atomicAdd(&g_gsum[cur * 64 + t], acc);
            if (t == 0) atomicAdd(&g_gcnt[cur], cnt);
            acc = 0.f; cnt = 0; cur = b;
        }
        acc += g_h2[node * 64 + t];
        cnt++;
    }
    atomicAdd(&g_gsum[cur * 64 + t], acc);
    if (t == 0) atomicAdd(&g_gcnt[cur], cnt);
}

// ---------------- head MLP: 64 -> 64 -> 16 -> 1 ------------------------------
__global__ void head_kernel(const float* __restrict__ p1w, const float* __restrict__ p1b,
                            const float* __restrict__ p2w, const float* __restrict__ p2b,
                            const float* __restrict__ ow,  const float* __restrict__ ob,
                            float* __restrict__ out) {
    int g = blockIdx.x, t = threadIdx.x;  // 64 threads
    __shared__ float sg[64], s1[64], s2[16];
    float c = (float)g_gcnt[g];
    float invc = 1.f / fmaxf(c, 1.f);
    sg[t] = g_gsum[g * 64 + t] * invc;
    __syncthreads();
    float acc = __ldg(&p1b[t]);
    #pragma unroll 8
    for (int k = 0; k < 64; k++) acc += sg[k] * __ldg(&p1w[k * 64 + t]);
    s1[t] = fmaxf(acc, 0.f);
    __syncthreads();
    if (t < 16) {
        float a2 = __ldg(&p2b[t]);
        #pragma unroll 8
        for (int k = 0; k < 64; k++) a2 += s1[k] * __ldg(&p2w[k * 16 + t]);
        s2[t] = fmaxf(a2, 0.f);
    }
    __syncthreads();
    if (t == 0) {
        float o = __ldg(&ob[0]);
        #pragma unroll
        for (int k = 0; k < 16; k++) o += s2[k] * __ldg(&ow[k]);
        out[g] = o;
    }
}

// ---------------- launcher ---------------------------------------------------
extern "C" void kernel_launch(void* const* d_in, const int* in_sizes, int n_in,
                              void* d_out, int out_size) {
    const float* x     = (const float*)d_in[0];
    const int*   ei    = (const int*)d_in[1];
    const int*   batch = (const int*)d_in[2];
    const float* pre_w = (const float*)d_in[4];
    const float* pre_b = (const float*)d_in[5];
    const float* c1_wl = (const float*)d_in[6];
    const float* c1_bl = (const float*)d_in[7];
    const float* c1_wr = (const float*)d_in[8];
    const float* c2_wl = (const float*)d_in[9];
    const float* c2_bl = (const float*)d_in[10];
    const float* c2_wr = (const float*)d_in[11];
    const float* p1_w  = (const float*)d_in[12];
    const float* p1_b  = (const float*)d_in[13];
    const float* p2_w  = (const float*)d_in[14];
    const float* p2_b  = (const float*)d_in[15];
    const float* o_w   = (const float*)d_in[16];
    const float* o_b   = (const float*)d_in[17];

    int n = in_sizes[0] / 5;          // nodes
    int E = in_sizes[1] / 2;          // edges
    int G = out_size;                 // graphs
    const int* src = ei;
    const int* dst = ei + E;
    float* out = (float*)d_out;

    int nb = (n + 1023) / 1024;

    zero_kernel<<<(n + 255) / 256, 256>>>(n, G);
    degree_kernel<<<(E + 255) / 256, 256>>>(dst, E);
    scan1_kernel<<<nb, 1024>>>(n);
    scan2_kernel<<<1, 1024>>>(nb, n);
    scan3_kernel<<<(n + 255) / 256, 256>>>(n);
    bucket_kernel<<<(E + 255) / 256, 256>>>(src, dst, E);
    pre_kernel<<<(n * 32 + 255) / 256, 256>>>(x, pre_w, pre_b, n);
    conv_kernel<1><<<(n + 15) / 16, 256>>>(c1_wl, c1_bl, c1_wr, n);
    conv_kernel<2><<<(n + 15) / 16, 256>>>(c2_wl, c2_bl, c2_wr, n);
    pool_kernel<<<(n + POOL_R - 1) / POOL_R, 64>>>(batch, n);
    head_kernel<<<G, 64>>>(p1_w, p1_b, p2_w, p2_b, o_w, o_b, out);
}

// round 3
// speedup vs baseline: 1.7639x; 1.1175x over previous
#include <cuda_runtime.h>
#include <cuda_bf16.h>
#include <cstdint>

#define N_NODES_MAX 100000
#define N_EDGES_MAX 1600000
#define N_GRAPHS_MAX 512

// ---------------- scratch (device globals; no allocation allowed) ----------
__device__ __align__(16) __nv_bfloat16 g_h0[N_NODES_MAX * 32];
__device__ __align__(16) __nv_bfloat16 g_h1[N_NODES_MAX * 64];
__device__ int   g_deg[N_NODES_MAX];
__device__ int   g_rowptr[N_NODES_MAX + 1];
__device__ int   g_wp[N_NODES_MAX];
__device__ int   g_src_sorted[N_EDGES_MAX];
__device__ int   g_bsum[1024];
__device__ int   g_boff[1024];
__device__ __align__(16) float g_gsum[N_GRAPHS_MAX * 64];
__device__ int   g_gcnt[N_GRAPHS_MAX];

// ---------------- degree count + graph node count ----------------------------
__global__ void degree_kernel(const int* __restrict__ dst,
                              const int* __restrict__ batch, int E, int n) {
    int i = blockIdx.x * blockDim.x + threadIdx.x;
    if (i < E) atomicAdd(&g_deg[dst[i]], 1);
    if (i < n) atomicAdd(&g_gcnt[batch[i]], 1);
}

// ---------------- multi-block scan, pass 1: per-block (1024) local scan ------
__global__ void scan1_kernel(int n) {
    __shared__ int warpsums[32];
    int t = threadIdx.x, lane = t & 31, w = t >> 5;
    int i = blockIdx.x * 1024 + t;
    int v = (i < n) ? g_deg[i] : 0;
    int x = v;
    #pragma unroll
    for (int off = 1; off < 32; off <<= 1) {
        int u = __shfl_up_sync(0xFFFFFFFFu, x, off);
        if (lane >= off) x += u;
    }
    if (lane == 31) warpsums[w] = x;
    __syncthreads();
    if (w == 0) {
        int y = warpsums[lane];
        #pragma unroll
        for (int off = 1; off < 32; off <<= 1) {
            int u = __shfl_up_sync(0xFFFFFFFFu, y, off);
            if (lane >= off) y += u;
        }
        warpsums[lane] = y;
    }
    __syncthreads();
    int woff = (w > 0) ? warpsums[w - 1] : 0;
    if (i < n) g_rowptr[i] = x + woff - v;   // local exclusive
    if (t == 0) g_bsum[blockIdx.x] = warpsums[31];
}

// ---------------- scan pass 2: scan the block sums (<=1024 blocks) ----------
__global__ void scan2_kernel(int nb, int n) {
    __shared__ int warpsums[32];
    int t = threadIdx.x, lane = t & 31, w = t >> 5;
    int v = (t < nb) ? g_bsum[t] : 0;
    int x = v;
    #pragma unroll
    for (int off = 1; off < 32; off <<= 1) {
        int u = __shfl_up_sync(0xFFFFFFFFu, x, off);
        if (lane >= off) x += u;
    }
    if (lane == 31) warpsums[w] = x;
    __syncthreads();
    if (w == 0) {
        int y = warpsums[lane];
        #pragma unroll
        for (int off = 1; off < 32; off <<= 1) {
            int u = __shfl_up_sync(0xFFFFFFFFu, y, off);
            if (lane >= off) y += u;
        }
        warpsums[lane] = y;
    }
    __syncthreads();
    int woff = (w > 0) ? warpsums[w - 1] : 0;
    if (t < nb) g_boff[t] = x + woff - v;
    if (t == 0) g_rowptr[n] = warpsums[31];
}

// ---------------- scan pass 3: add block offsets -----------------------------
__global__ void scan3_kernel(int n) {
    int i = blockIdx.x * blockDim.x + threadIdx.x;
    if (i < n) {
        int v = g_rowptr[i] + g_boff[i >> 10];
        g_rowptr[i] = v;
        g_wp[i] = v;
    }
}

// ---------------- bucket edges by dst ----------------------------------------
__global__ void bucket_kernel(const int* __restrict__ src,
                              const int* __restrict__ dst, int E) {
    int e = blockIdx.x * blockDim.x + threadIdx.x;
    if (e < E) {
        int d = dst[e];
        int p = atomicAdd(&g_wp[d], 1);
        g_src_sorted[p] = src[e];
    }
}

// ---------------- pre MLP: x[N,5] @ W[5,32] + b, relu -> bf16 ----------------
__global__ void pre_kernel(const float* __restrict__ x,
                           const float* __restrict__ w,
                           const float* __restrict__ b, int n) {
    int tid = blockIdx.x * blockDim.x + threadIdx.x;
    if (tid >= n * 32) return;
    int node = tid >> 5, j = tid & 31;
    const float* xr = x + node * 5;
    float acc = __ldg(&b[j]);
    #pragma unroll
    for (int k = 0; k < 5; k++) acc += xr[k] * __ldg(&w[k * 32 + j]);
    g_h0[tid] = __float2bfloat16(fmaxf(acc, 0.f));
}

// ---------------- conv1: bf16 h0 -> bf16 h1 ----------------------------------
// 2 nodes per warp. Weights packed float4 {wl[k][2o],wr[k][2o],wl[k][2o+1],wr[k][2o+1]}.
__global__ __launch_bounds__(256) void conv1_kernel(
    const float* __restrict__ wl, const float* __restrict__ bl,
    const float* __restrict__ wr, int n)
{
    __shared__ float4 sw4[32 * 32];
    __shared__ float  sb[64];
    __shared__ float4 sAH[8][2][32];

    for (int i = threadIdx.x; i < 32 * 32; i += blockDim.x) {
        int k = i >> 5, o2 = (i & 31) * 2;
        sw4[i] = make_float4(wl[k * 64 + o2],     wr[k * 64 + o2],
                             wl[k * 64 + o2 + 1], wr[k * 64 + o2 + 1]);
    }
    if (threadIdx.x < 64) sb[threadIdx.x] = bl[threadIdx.x];
    __syncthreads();

    int warp = threadIdx.x >> 5, lane = threadIdx.x & 31;
    int node0 = blockIdx.x * 16 + warp * 2;
    if (node0 >= n) return;
    int node1 = node0 + 1;
    bool hasB = (node1 < n);

    #pragma unroll
    for (int t = 0; t < 2; t++) {
        int node = node0 + t;
        if (t == 1 && !hasB) break;
        int s0 = g_rowptr[node], s1 = g_rowptr[node + 1];
        float a = 0.f;
        int e = s0;
        for (; e + 4 <= s1; e += 4) {
            int sa = g_src_sorted[e],     sbi = g_src_sorted[e + 1];
            int sc = g_src_sorted[e + 2], sd  = g_src_sorted[e + 3];
            float va = __bfloat162float(g_h0[sa * 32 + lane]);
            float vb = __bfloat162float(g_h0[sbi * 32 + lane]);
            float vc = __bfloat162float(g_h0[sc * 32 + lane]);
            float vd = __bfloat162float(g_h0[sd * 32 + lane]);
            a += (va + vb) + (vc + vd);
        }
        for (; e < s1; e++) a += __bfloat162float(g_h0[g_src_sorted[e] * 32 + lane]);
        float inv = (s1 > s0) ? 1.f / (float)(s1 - s0) : 0.f;
        a *= inv;
        float h = __bfloat162float(g_h0[node * 32 + lane]);
        sAH[warp][t][lane] = make_float4(a, h, 0.f, 0.f);
    }
    __syncwarp();

    float accA0 = sb[2 * lane], accA1 = sb[2 * lane + 1];
    float accB0 = accA0,        accB1 = accA1;
    #pragma unroll
    for (int k = 0; k < 32; k++) {
        float4 w = sw4[k * 32 + lane];
        float4 A = sAH[warp][0][k];
        float4 B = sAH[warp][1][k];
        accA0 += A.x * w.x + A.y * w.y;
        accA1 += A.x * w.z + A.y * w.w;
        accB0 += B.x * w.x + B.y * w.y;
        accB1 += B.x * w.z + B.y * w.w;
    }

    float ssA = accA0 * accA0 + accA1 * accA1;
    float ssB = accB0 * accB0 + accB1 * accB1;
    #pragma unroll
    for (int off = 16; off; off >>= 1) {
        ssA += __shfl_xor_sync(0xFFFFFFFFu, ssA, off);
        ssB += __shfl_xor_sync(0xFFFFFFFFu, ssB, off);
    }
    float invA = 1.f / fmaxf(sqrtf(ssA), 1e-12f);
    __nv_bfloat162* outp = (__nv_bfloat162*)&g_h1[node0 * 64 + 2 * lane];
    *outp = __floats2bfloat162_rn(fmaxf(accA0 * invA, 0.f), fmaxf(accA1 * invA, 0.f));
    if (hasB) {
        float invB = 1.f / fmaxf(sqrtf(ssB), 1e-12f);
        __nv_bfloat162* outq = (__nv_bfloat162*)&g_h1[node1 * 64 + 2 * lane];
        *outq = __floats2bfloat162_rn(fmaxf(accB0 * invB, 0.f), fmaxf(accB1 * invB, 0.f));
    }
}

// ---------------- conv2 + fused segmented global-mean-pool -------------------
__global__ __launch_bounds__(256) void conv2_kernel(
    const float* __restrict__ wl, const float* __restrict__ bl,
    const float* __restrict__ wr, const int* __restrict__ batch, int n)
{
    __shared__ float4 sw4[64 * 32];
    __shared__ float  sb[64];
    __shared__ float4 sAH[8][2][32];
    __shared__ float  s_out[16][64];
    __shared__ int    s_bid[16];

    for (int i = threadIdx.x; i < 64 * 32; i += blockDim.x) {
        int k = i >> 5, o2 = (i & 31) * 2;
        sw4[i] = make_float4(wl[k * 64 + o2],     wr[k * 64 + o2],
                             wl[k * 64 + o2 + 1], wr[k * 64 + o2 + 1]);
    }
    if (threadIdx.x < 64) sb[threadIdx.x] = bl[threadIdx.x];
    __syncthreads();

    int warp = threadIdx.x >> 5, lane = threadIdx.x & 31;
    int blockStart = blockIdx.x * 16;
    int nlocal = min(16, n - blockStart);
    int node0 = blockStart + warp * 2;
    int node1 = node0 + 1;
    bool hasA = (node0 < n);
    bool hasB = (node1 < n);

    if (hasA) {
        #pragma unroll
        for (int t = 0; t < 2; t++) {
            int node = node0 + t;
            if (t == 1 && !hasB) break;
            int s0 = g_rowptr[node], s1 = g_rowptr[node + 1];
            float ax_ = 0.f, ay_ = 0.f;
            int e = s0;
            for (; e + 4 <= s1; e += 4) {
                int sa = g_src_sorted[e],     sbi = g_src_sorted[e + 1];
                int sc = g_src_sorted[e + 2], sd  = g_src_sorted[e + 3];
                float2 va = __bfloat1622float2(*(const __nv_bfloat162*)&g_h1[sa  * 64 + 2 * lane]);
                float2 vb = __bfloat1622float2(*(const __nv_bfloat162*)&g_h1[sbi * 64 + 2 * lane]);
                float2 vc = __bfloat1622float2(*(const __nv_bfloat162*)&g_h1[sc  * 64 + 2 * lane]);
                float2 vd = __bfloat1622float2(*(const __nv_bfloat162*)&g_h1[sd  * 64 + 2 * lane]);
                ax_ += (va.x + vb.x) + (vc.x + vd.x);
                ay_ += (va.y + vb.y) + (vc.y + vd.y);
            }
            for (; e < s1; e++) {
                float2 v = __bfloat1622float2(*(const __nv_bfloat162*)&g_h1[g_src_sorted[e] * 64 + 2 * lane]);
                ax_ += v.x; ay_ += v.y;
            }
            float inv = (s1 > s0) ? 1.f / (float)(s1 - s0) : 0.f;
            ax_ *= inv; ay_ *= inv;
            float2 h = __bfloat1622float2(*(const __nv_bfloat162*)&g_h1[node * 64 + 2 * lane]);
            sAH[warp][t][lane] = make_float4(ax_, ay_, h.x, h.y);
        }
        __syncwarp();

        float accA0 = sb[2 * lane], accA1 = sb[2 * lane + 1];
        float accB0 = accA0,        accB1 = accA1;
        #pragma unroll
        for (int kp = 0; kp < 32; kp++) {
            float4 w0 = sw4[(2 * kp) * 32 + lane];
            float4 w1 = sw4[(2 * kp + 1) * 32 + lane];
            float4 A = sAH[warp][0][kp];
            float4 B = sAH[warp][1][kp];
            accA0 += A.x * w0.x + A.z * w0.y + A.y * w1.x + A.w * w1.y;
            accA1 += A.x * w0.z + A.z * w0.w + A.y * w1.z + A.w * w1.w;
            accB0 += B.x * w0.x + B.z * w0.y + B.y * w1.x + B.w * w1.y;
            accB1 += B.x * w0.z + B.z * w0.w + B.y * w1.z + B.w * w1.w;
        }

        float ssA = accA0 * accA0 + accA1 * accA1;
        float ssB = accB0 * accB0 + accB1 * accB1;
        #pragma unroll
        for (int off = 16; off; off >>= 1) {
            ssA += __shfl_xor_sync(0xFFFFFFFFu, ssA, off);
            ssB += __shfl_xor_sync(0xFFFFFFFFu, ssB, off);
        }
        float invA = 1.f / fmaxf(sqrtf(ssA), 1e-12f);
        s_out[warp * 2][2 * lane]     = fmaxf(accA0 * invA, 0.f);
        s_out[warp * 2][2 * lane + 1] = fmaxf(accA1 * invA, 0.f);
        if (lane == 0) s_bid[warp * 2] = batch[node0];
        if (hasB) {
            float invB = 1.f / fmaxf(sqrtf(ssB), 1e-12f);
            s_out[warp * 2 + 1][2 * lane]     = fmaxf(accB0 * invB, 0.f);
            s_out[warp * 2 + 1][2 * lane + 1] = fmaxf(accB1 * invB, 0.f);
            if (lane == 0) s_bid[warp * 2 + 1] = batch[node1];
        }
    }
    __syncthreads();

    // segmented flush: thread t owns dim d for a 4-node group (batch sorted)
    int d = threadIdx.x & 63;
    int grp = threadIdx.x >> 6;           // 4 groups x 4 nodes
    float acc = 0.f;
    int cur = -1;
    #pragma unroll
    for (int i = grp * 4; i < grp * 4 + 4; i++) {
        if (i >= nlocal) break;
        int b = s_bid[i];
        if (b != cur) {
            if (cur >= 0) atomicAdd(&g_gsum[cur * 64 + d], acc);
            cur = b; acc = 0.f;
        }
        acc += s_out[i][d];
    }
    if (cur >= 0) atomicAdd(&g_gsum[cur * 64 + d], acc);
}

// ---------------- head MLP: 64 -> 64 -> 16 -> 1 ------------------------------
__global__ void head_kernel(const float* __restrict__ p1w, const float* __restrict__ p1b,
                            const float* __restrict__ p2w, const float* __restrict__ p2b,
                            const float* __restrict__ ow,  const float* __restrict__ ob,
                            float* __restrict__ out) {
    int g = blockIdx.x, t = threadIdx.x;  // 64 threads
    __shared__ float sg[64], s1[64], s2[16];
    float c = (float)g_gcnt[g];
    float invc = 1.f / fmaxf(c, 1.f);
    sg[t] = g_gsum[g * 64 + t] * invc;
    __syncthreads();
    float acc = __ldg(&p1b[t]);
    #pragma unroll 8
    for (int k = 0; k < 64; k++) acc += sg[k] * __ldg(&p1w[k * 64 + t]);
    s1[t] = fmaxf(acc, 0.f);
    __syncthreads();
    if (t < 16) {
        float a2 = __ldg(&p2b[t]);
        #pragma unroll 8
        for (int k = 0; k < 64; k++) a2 += s1[k] * __ldg(&p2w[k * 16 + t]);
        s2[t] = fmaxf(a2, 0.f);
    }
    __syncthreads();
    if (t == 0) {
        float o = __ldg(&ob[0]);
        #pragma unroll
        for (int k = 0; k < 16; k++) o += s2[k] * __ldg(&ow[k]);
        out[g] = o;
    }
}

// ---------------- launcher ---------------------------------------------------
extern "C" void kernel_launch(void* const* d_in, const int* in_sizes, int n_in,
                              void* d_out, int out_size) {
    const float* x     = (const float*)d_in[0];
    const int*   ei    = (const int*)d_in[1];
    const int*   batch = (const int*)d_in[2];
    const float* pre_w = (const float*)d_in[4];
    const float* pre_b = (const float*)d_in[5];
    const float* c1_wl = (const float*)d_in[6];
    const float* c1_bl = (const float*)d_in[7];
    const float* c1_wr = (const float*)d_in[8];
    const float* c2_wl = (const float*)d_in[9];
    const float* c2_bl = (const float*)d_in[10];
    const float* c2_wr = (const float*)d_in[11];
    const float* p1_w  = (const float*)d_in[12];
    const float* p1_b  = (const float*)d_in[13];
    const float* p2_w  = (const float*)d_in[14];
    const float* p2_b  = (const float*)d_in[15];
    const float* o_w   = (const float*)d_in[16];
    const float* o_b   = (const float*)d_in[17];

    int n = in_sizes[0] / 5;          // nodes
    int E = in_sizes[1] / 2;          // edges
    int G = out_size;                 // graphs
    const int* src = ei;
    const int* dst = ei + E;
    float* out = (float*)d_out;

    int nb = (n + 1023) / 1024;

    void *p_deg = nullptr, *p_gsum = nullptr, *p_gcnt = nullptr;
    cudaGetSymbolAddress(&p_deg, g_deg);
    cudaGetSymbolAddress(&p_gsum, g_gsum);
    cudaGetSymbolAddress(&p_gcnt, g_gcnt);
    cudaMemsetAsync(p_deg, 0, n * sizeof(int), 0);
    cudaMemsetAsync(p_gsum, 0, G * 64 * sizeof(float), 0);
    cudaMemsetAsync(p_gcnt, 0, G * sizeof(int), 0);

    degree_kernel<<<(E + 255) / 256, 256>>>(dst, batch, E, n);
    scan1_kernel<<<nb, 1024>>>(n);
    scan2_kernel<<<1, 1024>>>(nb, n);
    scan3_kernel<<<(n + 255) / 256, 256>>>(n);
    bucket_kernel<<<(E + 255) / 256, 256>>>(src, dst, E);
    pre_kernel<<<(n * 32 + 255) / 256, 256>>>(x, pre_w, pre_b, n);
    conv1_kernel<<<(n + 15) / 16, 256>>>(c1_wl, c1_bl, c1_wr, n);
    conv2_kernel<<<(n + 15) / 16, 256>>>(c2_wl, c2_bl, c2_wr, batch, n);
    head_kernel<<<G, 64>>>(p1_w, p1_b, p2_w, p2_b, o_w, o_b, out);
}